// round 13
// baseline (speedup 1.0000x reference)
#include <cuda_runtime.h>
#include <cuda.h>
#include <cuda_bf16.h>
#include <math.h>
#include <stdint.h>

// ---------------- problem constants ----------------
#define BB 2048
#define CC 2048
#define NN 16384
#define INV_TEMP 20.0f
#define SCALE_LOG2E 28.853900817779268f   // (1/0.05) * log2(e)

// ---------------- tiling (tcgen05 path) ----------------
#define BM 256
#define BN 256
#define BKC 64                  // bf16 K elems per chunk (128 B per row)
#define NCHUNK (CC / BKC)       // 32
#define NSTAGE 3
#define NSPL 128                // partial slots per row = 64 nblk * 2 col-halves
#define STAGE_BYTES 65536       // A(32K) + B(32K)
#define DSMEM_BYTES (NSTAGE * STAGE_BYTES + 1024)
#define NTHREADS 544            // warps 0-15 epilogue (+w0l0 issuer), warp 16 TMA

// ---------------- device scratch ----------------
__device__ __align__(1024) __nv_bfloat16 g_A[BB * CC];      // 8 MB
__device__ __align__(1024) __nv_bfloat16 g_B[NN * CC];      // 64 MB
__device__ float g_pmin[BB * NSPL];
__device__ float g_nsum[BB * NSPL];
__device__ float g_loss[BB];
__device__ int   g_count = 0;

// tcgen05 only on arch-specific (sm_103a) pass; generic compute_103 pass gets
// a plain SIMT fallback so ptxas never sees tcgen05 on .target sm_103.
#if defined(__CUDA_ARCH__) && (__CUDA_ARCH__ >= 1000) && \
    (defined(__CUDA_ARCH_FEAT_SM103_ALL) || defined(__CUDA_ARCH_SPECIFIC__) || \
     defined(__CUDA_ARCH_FAMILY_SPECIFIC__))
#define USE_TCGEN05 1
#else
#define USE_TCGEN05 0
#endif

// ---------------- fused fp32 -> bf16 conversion (8 floats / thread) --------
#define NA8 (BB * CC / 8)
#define NB8 (NN * CC / 8)
__global__ void cvt_kernel(const float4* __restrict__ A, const float4* __restrict__ B) {
    int i = blockIdx.x * blockDim.x + threadIdx.x;
    const float4* src;
    uint4* dst;
    int j;
    if (i < NA8)            { j = i;       src = A; dst = (uint4*)g_A; }
    else if (i < NA8 + NB8) { j = i - NA8; src = B; dst = (uint4*)g_B; }
    else return;
    float4 v0 = src[2 * j];
    float4 v1 = src[2 * j + 1];
    __nv_bfloat162 o0 = __floats2bfloat162_rn(v0.x, v0.y);
    __nv_bfloat162 o1 = __floats2bfloat162_rn(v0.z, v0.w);
    __nv_bfloat162 o2 = __floats2bfloat162_rn(v1.x, v1.y);
    __nv_bfloat162 o3 = __floats2bfloat162_rn(v1.z, v1.w);
    uint4 pack;
    pack.x = *(uint32_t*)&o0;
    pack.y = *(uint32_t*)&o1;
    pack.z = *(uint32_t*)&o2;
    pack.w = *(uint32_t*)&o3;
    dst[j] = pack;
}

#if USE_TCGEN05
// ===========================================================================
// tcgen05 path (sm_103a): 256x256 tile, plain TMA, 3-stage ring,
// split roles: warp16 = producer, warp0-lane0 = issuer, 16 warps epilogue.
// ===========================================================================
__device__ __forceinline__ uint32_t smem_u32(const void* p) {
    uint32_t a;
    asm("{ .reg .u64 t; cvta.to.shared.u64 t, %1; cvt.u32.u64 %0, t; }" : "=r"(a) : "l"(p));
    return a;
}
__device__ __forceinline__ uint32_t elect_one() {
    uint32_t p;
    asm volatile("{ .reg .pred p; elect.sync _|p, 0xFFFFFFFF; selp.b32 %0, 1, 0, p; }" : "=r"(p));
    return p;
}
__device__ __forceinline__ float ex2f(float x) {
    float y; asm("ex2.approx.f32 %0, %1;" : "=f"(y) : "f"(x)); return y;
}

#define MBARRIER_INIT(addr, cnt) \
    asm volatile("mbarrier.init.shared.b64 [%0], %1;" :: "r"(addr), "r"(cnt) : "memory")

#define MBARRIER_EXPECT_TX(addr, bytes) \
    asm volatile("mbarrier.arrive.expect_tx.shared.b64 _, [%0], %1;" \
                 :: "r"(addr), "r"(bytes) : "memory")

#define MBARRIER_WAIT_PARITY(addr, par) do {                                   \
    uint32_t _m = (addr), _p = (par), _d;                                      \
    asm volatile("{ .reg .pred p;"                                             \
        "mbarrier.try_wait.parity.acquire.cta.shared::cta.b64 p, [%1], %2;"    \
        "selp.b32 %0, 1, 0, p; }" : "=r"(_d) : "r"(_m), "r"(_p) : "memory");   \
    if (!_d) {                                                                 \
        asm volatile("{ .reg .pred P1; WL_%=:"                                 \
        "mbarrier.try_wait.parity.acquire.cta.shared::cta.b64 P1, [%0], %1, 0x989680;" \
        "@P1 bra.uni WD_%=; bra.uni WL_%=; WD_%=: }"                           \
        :: "r"(_m), "r"(_p) : "memory");                                       \
    }                                                                          \
} while (0)

#define TMA_2D(dst, map, x, y, mb) \
    asm volatile("cp.async.bulk.tensor.2d.shared::cta.global.tile.mbarrier::complete_tx::bytes " \
        "[%0], [%1, {%2, %3}], [%4];" \
        :: "r"(dst), "l"(map), "r"(x), "r"(y), "r"(mb) : "memory")

#define TCGEN05_ALLOC(slot, ncols) \
    asm volatile("tcgen05.alloc.cta_group::1.sync.aligned.shared::cta.b32 [%0], %1;" \
                 :: "r"(slot), "r"(ncols) : "memory")
#define TCGEN05_DEALLOC(tmem, ncols) \
    asm volatile("tcgen05.dealloc.cta_group::1.sync.aligned.b32 %0, %1;" :: "r"(tmem), "r"(ncols))
#define TCGEN05_RELINQ() \
    asm volatile("tcgen05.relinquish_alloc_permit.cta_group::1.sync.aligned;")
#define TCGEN05_COMMIT(mb) \
    asm volatile("tcgen05.commit.cta_group::1.mbarrier::arrive::one.shared::cluster.b64 [%0];" \
                 :: "r"(mb) : "memory")
#define TCGEN05_FENCE_AFTER() asm volatile("tcgen05.fence::after_thread_sync;" ::: "memory")
#define TCGEN05_WAIT_LD()     asm volatile("tcgen05.wait::ld.sync.aligned;" ::: "memory")

#define TCGEN05_LD_X32(r, addr) \
    asm volatile("tcgen05.ld.sync.aligned.32x32b.x32.b32 " \
        "{%0,%1,%2,%3,%4,%5,%6,%7,%8,%9,%10,%11,%12,%13,%14,%15," \
        "%16,%17,%18,%19,%20,%21,%22,%23,%24,%25,%26,%27,%28,%29,%30,%31}, [%32];" \
        : "=r"((r)[0]),"=r"((r)[1]),"=r"((r)[2]),"=r"((r)[3]),"=r"((r)[4]),"=r"((r)[5]), \
          "=r"((r)[6]),"=r"((r)[7]),"=r"((r)[8]),"=r"((r)[9]),"=r"((r)[10]),"=r"((r)[11]), \
          "=r"((r)[12]),"=r"((r)[13]),"=r"((r)[14]),"=r"((r)[15]),"=r"((r)[16]),"=r"((r)[17]), \
          "=r"((r)[18]),"=r"((r)[19]),"=r"((r)[20]),"=r"((r)[21]),"=r"((r)[22]),"=r"((r)[23]), \
          "=r"((r)[24]),"=r"((r)[25]),"=r"((r)[26]),"=r"((r)[27]),"=r"((r)[28]),"=r"((r)[29]), \
          "=r"((r)[30]),"=r"((r)[31]) : "r"(addr))

// idesc: f32 accum, bf16 A/B, N=128, M=128
#define IDESC ((1u << 4) | (1u << 7) | (1u << 10) | (16u << 17) | (8u << 24))

__device__ __forceinline__ uint64_t make_desc(uint32_t addr) {
    return (2ull << 61) | (1ull << 46) | (64ull << 32) | (1ull << 16)
         | ((uint64_t)(addr >> 4) & 0x3FFF);
}

__device__ __forceinline__ void mma_f16_ss(uint32_t d, uint64_t a, uint64_t b,
                                           uint32_t idesc, uint32_t acc) {
    asm volatile("{ .reg .pred p; setp.ne.u32 p, %5, 0;"
        "tcgen05.mma.cta_group::1.kind::f16 [%0], %1, %2, %3, {%4,%4,%4,%4}, p; }"
        :: "r"(d), "l"(a), "l"(b), "r"(idesc), "r"(0u), "r"(acc) : "memory");
}

__global__ __launch_bounds__(NTHREADS)
void gemm_kernel(const __grid_constant__ CUtensorMap mapA,
                 const __grid_constant__ CUtensorMap mapB,
                 const int* __restrict__ labels, const int* __restrict__ labels_s)
{
    extern __shared__ char dsm[];
    __shared__ uint64_t full_b[NSTAGE], empty_b[NSTAGE], done_b;
    __shared__ uint32_t tmem_slot;
    __shared__ int slab[BN];

    const int nblk = blockIdx.x;           // 0..63
    const int mblk = blockIdx.y;           // 0..7
    const int row0 = mblk * BM;
    const int col0 = nblk * BN;
    const int tid  = threadIdx.x;
    const int wid  = tid >> 5;

    char* sm = (char*)(((uintptr_t)dsm + 1023) & ~(uintptr_t)1023);
    const uint32_t smb = smem_u32(sm);
    const uint32_t done_a = smem_u32(&done_b);

    if (wid == 0) TCGEN05_ALLOC(smem_u32(&tmem_slot), 512);
    if (tid == 0) {
        #pragma unroll
        for (int s = 0; s < NSTAGE; ++s) {
            MBARRIER_INIT(smem_u32(&full_b[s]), 1);   // 1 arrival/round via expect_tx
            MBARRIER_INIT(smem_u32(&empty_b[s]), 1);  // local commit only
        }
        MBARRIER_INIT(done_a, 1);
    }
    if (tid < BN) slab[tid] = labels_s[col0 + tid];
    __syncthreads();
    const uint32_t tmem = tmem_slot;

    if (wid == 16) {
        // --------------- TMA producer: never waits on full ---------------
        if (elect_one()) {
            int s = 0, u = 0;
            for (int k = 0; k < NCHUNK; ++k) {
                if (k >= NSTAGE)
                    MBARRIER_WAIT_PARITY(smem_u32(&empty_b[s]), (u - 1) & 1);
                const uint32_t sb = smb + s * STAGE_BYTES;
                const uint32_t fb = smem_u32(&full_b[s]);
                MBARRIER_EXPECT_TX(fb, STAGE_BYTES);
                TMA_2D(sb,         &mapA, k * BKC, row0,       fb);
                TMA_2D(sb + 32768, &mapB, k * BKC, col0,       fb);
                TMA_2D(sb + 49152, &mapB, k * BKC, col0 + 128, fb);
                if (++s == NSTAGE) { s = 0; ++u; }
            }
        }
    } else if (tid == 0) {
        // --------------- MMA issuer: never waits on empty ---------------
        int s = 0, u = 0;
        for (int k = 0; k < NCHUNK; ++k) {
            MBARRIER_WAIT_PARITY(smem_u32(&full_b[s]), u & 1);
            asm volatile("fence.proxy.async.shared::cta;" ::: "memory");
            const uint32_t sb = smb + s * STAGE_BYTES;
            uint64_t a0 = make_desc(sb);
            uint64_t a1 = make_desc(sb + 16384);
            uint64_t b0 = make_desc(sb + 32768);
            uint64_t b1 = make_desc(sb + 49152);
            #pragma unroll
            for (int ks = 0; ks < 4; ++ks) {
                uint32_t acc = (k > 0 || ks > 0) ? 1u : 0u;
                mma_f16_ss(tmem,       a0 + ks * 2, b0 + ks * 2, IDESC, acc);
                mma_f16_ss(tmem + 128, a0 + ks * 2, b1 + ks * 2, IDESC, acc);
                mma_f16_ss(tmem + 256, a1 + ks * 2, b0 + ks * 2, IDESC, acc);
                mma_f16_ss(tmem + 384, a1 + ks * 2, b1 + ks * 2, IDESC, acc);
            }
            TCGEN05_COMMIT(smem_u32(&empty_b[s]));
            if (++s == NSTAGE) { s = 0; ++u; }
        }
        TCGEN05_COMMIT(done_a);
    }

    // --------- wait for all MMAs, then 16-warp epilogue ---------
    if (wid < 16) {
        MBARRIER_WAIT_PARITY(done_a, 0);
        TCGEN05_FENCE_AFTER();

        const int lane = tid & 31;
        const int sub  = wid & 3;          // TMEM subpartition
        const int mh   = (wid >> 2) & 1;   // M-half
        const int ch   = wid >> 3;         // col half (0: B0 cols, 1: B1 cols)
        const uint32_t dbase = tmem + mh * 256 + ch * 128 + ((uint32_t)sub << 21);
        const int rowg = row0 + mh * 128 + sub * 32 + lane;
        const int lab  = labels[rowg];

        float smin = INFINITY, nsum = 0.0f;
        #pragma unroll
        for (int cb = 0; cb < 4; ++cb) {
            uint32_t regs[32];
            TCGEN05_LD_X32(regs, dbase + cb * 32);
            TCGEN05_WAIT_LD();
            #pragma unroll
            for (int c = 0; c < 32; ++c) {
                float sv = __uint_as_float(regs[c]);
                int cl = slab[ch * 128 + cb * 32 + c];
                if (cl == lab) smin = fminf(smin, sv);
                else           nsum += ex2f(sv * SCALE_LOG2E);
            }
        }
        float pmin = ex2f(smin * SCALE_LOG2E);
        size_t slot = (size_t)rowg * NSPL + nblk * 2 + ch;
        g_pmin[slot] = pmin;
        g_nsum[slot] = nsum;
    }

    __syncthreads();
    if (wid == 0) { TCGEN05_RELINQ(); TCGEN05_DEALLOC(tmem, 512); }
}

#else
// ===========================================================================
// Fallback (plain sm_103 pass only; never selected at runtime on GB300)
// ===========================================================================
__global__ __launch_bounds__(NTHREADS)
void gemm_kernel(const __grid_constant__ CUtensorMap mapA,
                 const __grid_constant__ CUtensorMap mapB,
                 const int* __restrict__ labels, const int* __restrict__ labels_s)
{
    __shared__ float As[16][64];
    __shared__ float Bs[16][64];
    __shared__ float red_min[64][16];
    __shared__ float red_sum[64][16];

    const int tid  = threadIdx.x;
    if (tid >= 256) return;
    const int nblk = blockIdx.x;   // 0..63
    const int mblk = blockIdx.y;   // 0..7
    const int tx   = tid & 15;
    const int ty   = tid >> 4;
    const int lr   = tid >> 2;
    const int lk4  = (tid & 3) * 4;

    for (int msub = 0; msub < 4; ++msub) {
        const int row0 = mblk * BM + msub * 64;
        int labr[4];
        #pragma unroll
        for (int i = 0; i < 4; ++i) labr[i] = labels[row0 + ty * 4 + i];

        for (int half = 0; half < 2; ++half) {
            float fm = INFINITY, fs = 0.0f;
            for (int nsub = 0; nsub < 2; ++nsub) {
                const int col0 = nblk * BN + half * 128 + nsub * 64;
                int labc[4];
                #pragma unroll
                for (int j = 0; j < 4; ++j) labc[j] = labels_s[col0 + tx * 4 + j];

                float acc[4][4];
                #pragma unroll
                for (int i = 0; i < 4; ++i)
                    #pragma unroll
                    for (int j = 0; j < 4; ++j) acc[i][j] = 0.0f;

                for (int k0 = 0; k0 < CC; k0 += 16) {
                    const __nv_bfloat162* ap = (const __nv_bfloat162*)
                        (g_A + (size_t)(row0 + lr) * CC + k0 + lk4);
                    const __nv_bfloat162* bp = (const __nv_bfloat162*)
                        (g_B + (size_t)(col0 + lr) * CC + k0 + lk4);
                    __nv_bfloat162 a01 = ap[0], a23 = ap[1];
                    __nv_bfloat162 b01 = bp[0], b23 = bp[1];
                    __syncthreads();
                    As[lk4 + 0][lr] = __bfloat162float(a01.x);
                    As[lk4 + 1][lr] = __bfloat162float(a01.y);
                    As[lk4 + 2][lr] = __bfloat162float(a23.x);
                    As[lk4 + 3][lr] = __bfloat162float(a23.y);
                    Bs[lk4 + 0][lr] = __bfloat162float(b01.x);
                    Bs[lk4 + 1][lr] = __bfloat162float(b01.y);
                    Bs[lk4 + 2][lr] = __bfloat162float(b23.x);
                    Bs[lk4 + 3][lr] = __bfloat162float(b23.y);
                    __syncthreads();
                    #pragma unroll
                    for (int kk = 0; kk < 16; ++kk) {
                        float4 a = *(const float4*)&As[kk][ty * 4];
                        float4 b = *(const float4*)&Bs[kk][tx * 4];
                        acc[0][0] += a.x * b.x; acc[0][1] += a.x * b.y;
                        acc[0][2] += a.x * b.z; acc[0][3] += a.x * b.w;
                        acc[1][0] += a.y * b.x; acc[1][1] += a.y * b.y;
                        acc[1][2] += a.y * b.z; acc[1][3] += a.y * b.w;
                        acc[2][0] += a.z * b.x; acc[2][1] += a.z * b.y;
                        acc[2][2] += a.z * b.z; acc[2][3] += a.z * b.w;
                        acc[3][0] += a.w * b.x; acc[3][1] += a.w * b.y;
                        acc[3][2] += a.w * b.z; acc[3][3] += a.w * b.w;
                    }
                }

                #pragma unroll
                for (int i = 0; i < 4; ++i) {
                    float pmin = INFINITY, nsum = 0.0f;
                    #pragma unroll
                    for (int j = 0; j < 4; ++j) {
                        float e = expf(acc[i][j] * INV_TEMP);
                        if (labr[i] == labc[j]) pmin = fminf(pmin, e);
                        else                    nsum += e;
                    }
                    red_min[ty * 4 + i][tx] = pmin;
                    red_sum[ty * 4 + i][tx] = nsum;
                }
                __syncthreads();
                if (tid < 64) {
                    #pragma unroll
                    for (int t = 0; t < 16; ++t) {
                        fm = fminf(fm, red_min[tid][t]);
                        fs += red_sum[tid][t];
                    }
                }
                __syncthreads();
            }
            if (tid < 64) {
                size_t slot = (size_t)(row0 + tid) * NSPL + nblk * 2 + half;
                g_pmin[slot] = fm;
                g_nsum[slot] = fs;
            }
        }
    }
}
#endif  // USE_TCGEN05

// ---------------- fused per-row loss + mean (last-block reduction) ----------
__global__ void loss_kernel(float* __restrict__ out)
{
    __shared__ float red[256];
    __shared__ int amLast;
    const int tid  = threadIdx.x;
    const int lane = tid & 31;
    const int row  = blockIdx.x * 8 + (tid >> 5);

    float4 pm = ((const float4*)(g_pmin + (size_t)row * NSPL))[lane];
    float4 ns = ((const float4*)(g_nsum + (size_t)row * NSPL))[lane];
    float m = fminf(fminf(pm.x, pm.y), fminf(pm.z, pm.w));
    float s = (ns.x + ns.y) + (ns.z + ns.w);
    #pragma unroll
    for (int off = 16; off > 0; off >>= 1) {
        m = fminf(m, __shfl_xor_sync(0xFFFFFFFF, m, off));
        s += __shfl_xor_sync(0xFFFFFFFF, s, off);
    }
    if (lane == 0)
        g_loss[row] = -logf(m / (m + s + 1e-6f) + 1e-6f);

    __threadfence();
    __syncthreads();
    if (tid == 0) amLast = (atomicAdd(&g_count, 1) == (BB / 8) - 1);
    __syncthreads();
    if (amLast) {
        __threadfence();
        float s2 = 0.0f;
        for (int r = tid; r < BB; r += 256) s2 += g_loss[r];
        red[tid] = s2;
        __syncthreads();
        for (int off = 128; off > 0; off >>= 1) {
            if (tid < off) red[tid] += red[tid + off];
            __syncthreads();
        }
        if (tid == 0) { out[0] = red[0] / (float)BB; g_count = 0; }
    }
}

// ---------------- host ----------------
typedef CUresult (*PFN_tmEncode)(
    CUtensorMap*, CUtensorMapDataType, cuuint32_t, void*,
    const cuuint64_t*, const cuuint64_t*, const cuuint32_t*, const cuuint32_t*,
    CUtensorMapInterleave, CUtensorMapSwizzle, CUtensorMapL2promotion,
    CUtensorMapFloatOOBfill);

extern "C" void kernel_launch(void* const* d_in, const int* in_sizes, int n_in,
                              void* d_out, int out_size)
{
    const float* feats    = (const float*)d_in[0];
    const float* feats_s  = (const float*)d_in[1];
    const int*   labels   = (const int*)d_in[2];
    const int*   labels_s = (const int*)d_in[3];
    float* out = (float*)d_out;

    cudaFuncSetAttribute(gemm_kernel, cudaFuncAttributeMaxDynamicSharedMemorySize,
                         DSMEM_BYTES);

    // Build TMA descriptors (pure host work; no device alloc).
    void *pA = nullptr, *pB = nullptr;
    cudaGetSymbolAddress(&pA, g_A);
    cudaGetSymbolAddress(&pB, g_B);
    PFN_tmEncode enc = nullptr;
    cudaDriverEntryPointQueryResult qr;
    cudaGetDriverEntryPoint("cuTensorMapEncodeTiled", (void**)&enc,
                            cudaEnableDefault, &qr);
    CUtensorMap mapA, mapB;
    {
        cuuint64_t dims[2]  = {CC, BB};
        cuuint64_t strides[1] = {CC * 2};
        cuuint32_t box[2]   = {64, 256};
        cuuint32_t es[2]    = {1, 1};
        enc(&mapA, CU_TENSOR_MAP_DATA_TYPE_BFLOAT16, 2, pA, dims, strides, box, es,
            CU_TENSOR_MAP_INTERLEAVE_NONE, CU_TENSOR_MAP_SWIZZLE_128B,
            CU_TENSOR_MAP_L2_PROMOTION_L2_128B, CU_TENSOR_MAP_FLOAT_OOB_FILL_NONE);
    }
    {
        cuuint64_t dims[2]  = {CC, NN};
        cuuint64_t strides[1] = {CC * 2};
        cuuint32_t box[2]   = {64, 128};
        cuuint32_t es[2]    = {1, 1};
        enc(&mapB, CU_TENSOR_MAP_DATA_TYPE_BFLOAT16, 2, pB, dims, strides, box, es,
            CU_TENSOR_MAP_INTERLEAVE_NONE, CU_TENSOR_MAP_SWIZZLE_128B,
            CU_TENSOR_MAP_L2_PROMOTION_L2_128B, CU_TENSOR_MAP_FLOAT_OOB_FILL_NONE);
    }

    cvt_kernel<<<(NA8 + NB8 + 255) / 256, 256>>>((const float4*)feats,
                                                 (const float4*)feats_s);
    dim3 grid(NN / BN, BB / BM);   // (64, 8)
    gemm_kernel<<<grid, NTHREADS, DSMEM_BYTES>>>(mapA, mapB, labels, labels_s);
    loss_kernel<<<BB / 8, 256>>>(out);
}

// round 14
// speedup vs baseline: 1.6383x; 1.6383x over previous
#include <cuda_runtime.h>
#include <cuda_bf16.h>
#include <math.h>
#include <stdint.h>

// ---------------- problem constants ----------------
#define BB 2048
#define CC 2048
#define NN 16384
#define INV_TEMP 20.0f
#define SCALE_LOG2E 28.853900817779268f   // (1/0.05) * log2(e)

// ---------------- tiling (tcgen05 path) ----------------
#define BM 256
#define BN 256
#define BKC 64                  // bf16 K elems per chunk (128 B per row)
#define NCHUNK (CC / BKC)       // 32
#define NSTAGE 3
#define NSPL 64                 // partial slots per row = NN/BN
#define STAGE_BYTES 65536       // A0,A1,B0,B1 (16K each)
#define DSMEM_BYTES (NSTAGE * STAGE_BYTES + 1024)
#define NTHREADS 288            // warps 0-7 load + epilogue, warp 8 = MMA

// ---------------- device scratch ----------------
__device__ __nv_bfloat16 g_A[BB * CC];      // 8 MB
__device__ __nv_bfloat16 g_B[NN * CC];      // 64 MB
__device__ float g_pmin[BB * NSPL];
__device__ float g_nsum[BB * NSPL];
__device__ float g_loss[BB];
__device__ int   g_count = 0;

// tcgen05 only on arch-specific (sm_103a) pass; generic compute_103 pass gets
// a plain SIMT fallback so ptxas never sees tcgen05 on .target sm_103.
#if defined(__CUDA_ARCH__) && (__CUDA_ARCH__ >= 1000) && \
    (defined(__CUDA_ARCH_FEAT_SM103_ALL) || defined(__CUDA_ARCH_SPECIFIC__) || \
     defined(__CUDA_ARCH_FAMILY_SPECIFIC__))
#define USE_TCGEN05 1
#else
#define USE_TCGEN05 0
#endif

// ---------------- fused fp32 -> bf16 conversion (8 floats / thread) --------
#define NA8 (BB * CC / 8)
#define NB8 (NN * CC / 8)
__global__ void cvt_kernel(const float4* __restrict__ A, const float4* __restrict__ B) {
    int i = blockIdx.x * blockDim.x + threadIdx.x;
    const float4* src;
    uint4* dst;
    int j;
    if (i < NA8)            { j = i;       src = A; dst = (uint4*)g_A; }
    else if (i < NA8 + NB8) { j = i - NA8; src = B; dst = (uint4*)g_B; }
    else return;
    float4 v0 = src[2 * j];
    float4 v1 = src[2 * j + 1];
    __nv_bfloat162 o0 = __floats2bfloat162_rn(v0.x, v0.y);
    __nv_bfloat162 o1 = __floats2bfloat162_rn(v0.z, v0.w);
    __nv_bfloat162 o2 = __floats2bfloat162_rn(v1.x, v1.y);
    __nv_bfloat162 o3 = __floats2bfloat162_rn(v1.z, v1.w);
    uint4 pack;
    pack.x = *(uint32_t*)&o0;
    pack.y = *(uint32_t*)&o1;
    pack.z = *(uint32_t*)&o2;
    pack.w = *(uint32_t*)&o3;
    dst[j] = pack;
}

#if USE_TCGEN05
// ===========================================================================
// tcgen05 path (sm_103a): 256x256 tile, warp-specialized 3-stage cp.async
// (exact R7 configuration — best measured: 147.8us total, gemm ~104us)
// ===========================================================================
__device__ __forceinline__ uint32_t smem_u32(const void* p) {
    uint32_t a;
    asm("{ .reg .u64 t; cvta.to.shared.u64 t, %1; cvt.u32.u64 %0, t; }" : "=r"(a) : "l"(p));
    return a;
}
__device__ __forceinline__ uint32_t elect_one() {
    uint32_t p;
    asm volatile("{ .reg .pred p; elect.sync _|p, 0xFFFFFFFF; selp.b32 %0, 1, 0, p; }" : "=r"(p));
    return p;
}
__device__ __forceinline__ float ex2f(float x) {
    float y; asm("ex2.approx.f32 %0, %1;" : "=f"(y) : "f"(x)); return y;
}

#define MBARRIER_INIT(addr, cnt) \
    asm volatile("mbarrier.init.shared.b64 [%0], %1;" :: "r"(addr), "r"(cnt) : "memory")

#define MBARRIER_WAIT_PARITY(addr, par) do {                                   \
    uint32_t _m = (addr), _p = (par), _d;                                      \
    asm volatile("{ .reg .pred p;"                                             \
        "mbarrier.try_wait.parity.acquire.cta.shared::cta.b64 p, [%1], %2;"    \
        "selp.b32 %0, 1, 0, p; }" : "=r"(_d) : "r"(_m), "r"(_p) : "memory");   \
    if (!_d) {                                                                 \
        asm volatile("{ .reg .pred P1; WL_%=:"                                 \
        "mbarrier.try_wait.parity.acquire.cta.shared::cta.b64 P1, [%0], %1, 0x989680;" \
        "@P1 bra.uni WD_%=; bra.uni WL_%=; WD_%=: }"                           \
        :: "r"(_m), "r"(_p) : "memory");                                       \
    }                                                                          \
} while (0)

#define CP_ASYNC16(dst, src) \
    asm volatile("cp.async.cg.shared.global [%0], [%1], 16;" \
                 :: "r"(dst), "l"(src) : "memory")
#define CP_ASYNC_ARRIVE_NOINC(mb) \
    asm volatile("cp.async.mbarrier.arrive.noinc.shared.b64 [%0];" :: "r"(mb) : "memory")

#define TCGEN05_ALLOC(slot, ncols) \
    asm volatile("tcgen05.alloc.cta_group::1.sync.aligned.shared::cta.b32 [%0], %1;" \
                 :: "r"(slot), "r"(ncols) : "memory")
#define TCGEN05_DEALLOC(tmem, ncols) \
    asm volatile("tcgen05.dealloc.cta_group::1.sync.aligned.b32 %0, %1;" :: "r"(tmem), "r"(ncols))
#define TCGEN05_RELINQ() \
    asm volatile("tcgen05.relinquish_alloc_permit.cta_group::1.sync.aligned;")
#define TCGEN05_COMMIT(mb) \
    asm volatile("tcgen05.commit.cta_group::1.mbarrier::arrive::one.shared::cluster.b64 [%0];" \
                 :: "r"(mb) : "memory")
#define TCGEN05_FENCE_AFTER() asm volatile("tcgen05.fence::after_thread_sync;" ::: "memory")
#define TCGEN05_WAIT_LD()     asm volatile("tcgen05.wait::ld.sync.aligned;" ::: "memory")

#define TCGEN05_LD_X32(r, addr) \
    asm volatile("tcgen05.ld.sync.aligned.32x32b.x32.b32 " \
        "{%0,%1,%2,%3,%4,%5,%6,%7,%8,%9,%10,%11,%12,%13,%14,%15," \
        "%16,%17,%18,%19,%20,%21,%22,%23,%24,%25,%26,%27,%28,%29,%30,%31}, [%32];" \
        : "=r"((r)[0]),"=r"((r)[1]),"=r"((r)[2]),"=r"((r)[3]),"=r"((r)[4]),"=r"((r)[5]), \
          "=r"((r)[6]),"=r"((r)[7]),"=r"((r)[8]),"=r"((r)[9]),"=r"((r)[10]),"=r"((r)[11]), \
          "=r"((r)[12]),"=r"((r)[13]),"=r"((r)[14]),"=r"((r)[15]),"=r"((r)[16]),"=r"((r)[17]), \
          "=r"((r)[18]),"=r"((r)[19]),"=r"((r)[20]),"=r"((r)[21]),"=r"((r)[22]),"=r"((r)[23]), \
          "=r"((r)[24]),"=r"((r)[25]),"=r"((r)[26]),"=r"((r)[27]),"=r"((r)[28]),"=r"((r)[29]), \
          "=r"((r)[30]),"=r"((r)[31]) : "r"(addr))

// idesc: f32 accum, bf16 A/B, N=128, M=128
#define IDESC ((1u << 4) | (1u << 7) | (1u << 10) | (16u << 17) | (8u << 24))

__device__ __forceinline__ uint64_t make_desc(uint32_t addr) {
    return (2ull << 61) | (1ull << 46) | (64ull << 32) | (1ull << 16)
         | ((uint64_t)(addr >> 4) & 0x3FFF);
}
__device__ __forceinline__ uint32_t swz(uint32_t o) { return o ^ ((o >> 3) & 0x70); }

__device__ __forceinline__ void mma_f16_ss(uint32_t d, uint64_t a, uint64_t b,
                                           uint32_t idesc, uint32_t acc) {
    asm volatile("{ .reg .pred p; setp.ne.u32 p, %5, 0;"
        "tcgen05.mma.cta_group::1.kind::f16 [%0], %1, %2, %3, {%4,%4,%4,%4}, p; }"
        :: "r"(d), "l"(a), "l"(b), "r"(idesc), "r"(0u), "r"(acc) : "memory");
}

__global__ __launch_bounds__(NTHREADS)
void gemm_kernel(const int* __restrict__ labels, const int* __restrict__ labels_s)
{
    extern __shared__ char dsm[];
    __shared__ uint64_t full_b[NSTAGE], empty_b[NSTAGE], done_b;
    __shared__ uint32_t tmem_slot;
    __shared__ int slab[BN];

    const int nblk = blockIdx.x;           // 0..63
    const int mblk = blockIdx.y;           // 0..7
    const int row0 = mblk * BM;
    const int col0 = nblk * BN;
    const int tid  = threadIdx.x;
    const int wid  = tid >> 5;

    char* sm = (char*)(((uintptr_t)dsm + 1023) & ~(uintptr_t)1023);
    const uint32_t smb = smem_u32(sm);
    const uint32_t done_a = smem_u32(&done_b);

    if (wid == 0) TCGEN05_ALLOC(smem_u32(&tmem_slot), 512);
    if (tid == 0) {
        #pragma unroll
        for (int s = 0; s < NSTAGE; ++s) {
            MBARRIER_INIT(smem_u32(&full_b[s]), 256);
            MBARRIER_INIT(smem_u32(&empty_b[s]), 1);
        }
        MBARRIER_INIT(done_a, 1);
    }
    if (tid < BN) slab[tid] = labels_s[col0 + tid];
    __syncthreads();
    const uint32_t tmem = tmem_slot;

    if (wid < 8) {
        // --------- producer: 256 threads, 16 x cp.async16 per chunk ---------
        // stage layout: A0 @0, A1 @16K, B0 @32K, B1 @48K; rows 128B SW128
        const char* srcs[16];
        uint32_t dsts[16];
        #pragma unroll
        for (int t = 0; t < 16; ++t) {
            int idx = tid + t * 256;          // 0..4095
            if (idx < 2048) {                 // A rows 0..255
                int r = idx >> 3, sg = idx & 7;
                srcs[t] = (const char*)(g_A + (size_t)(row0 + r) * CC + sg * 8);
                dsts[t] = (r >> 7) * 16384 + swz((r & 127) * 128 + sg * 16);
            } else {                          // B rows 0..255
                int i2 = idx - 2048;
                int r = i2 >> 3, sg = i2 & 7;
                srcs[t] = (const char*)(g_B + (size_t)(col0 + r) * CC + sg * 8);
                dsts[t] = 32768 + (r >> 7) * 16384 + swz((r & 127) * 128 + sg * 16);
            }
        }
        int s = 0, u = 0;
        for (int k = 0; k < NCHUNK; ++k) {
            if (u > 0) MBARRIER_WAIT_PARITY(smem_u32(&empty_b[s]), (u - 1) & 1);
            const uint32_t sb = smb + s * STAGE_BYTES;
            const int koff = k * (BKC * 2);   // bytes along K
            #pragma unroll
            for (int t = 0; t < 16; ++t) CP_ASYNC16(sb + dsts[t], srcs[t] + koff);
            CP_ASYNC_ARRIVE_NOINC(smem_u32(&full_b[s]));
            if (++s == NSTAGE) { s = 0; ++u; }
        }
    } else {
        // --------- MMA issuer: warp 8, elected lane ---------
        if (elect_one()) {
            int s = 0, u = 0;
            for (int k = 0; k < NCHUNK; ++k) {
                MBARRIER_WAIT_PARITY(smem_u32(&full_b[s]), u & 1);
                asm volatile("fence.proxy.async.shared::cta;" ::: "memory");
                const uint32_t sb = smb + s * STAGE_BYTES;
                uint64_t a0 = make_desc(sb);
                uint64_t a1 = make_desc(sb + 16384);
                uint64_t b0 = make_desc(sb + 32768);
                uint64_t b1 = make_desc(sb + 49152);
                #pragma unroll
                for (int ks = 0; ks < 4; ++ks) {
                    uint32_t acc = (k > 0 || ks > 0) ? 1u : 0u;
                    mma_f16_ss(tmem,       a0 + ks * 2, b0 + ks * 2, IDESC, acc);
                    mma_f16_ss(tmem + 128, a0 + ks * 2, b1 + ks * 2, IDESC, acc);
                    mma_f16_ss(tmem + 256, a1 + ks * 2, b0 + ks * 2, IDESC, acc);
                    mma_f16_ss(tmem + 384, a1 + ks * 2, b1 + ks * 2, IDESC, acc);
                }
                TCGEN05_COMMIT(smem_u32(&empty_b[s]));
                if (++s == NSTAGE) { s = 0; ++u; }
            }
            TCGEN05_COMMIT(done_a);
        }
    }

    // --------- wait for all MMAs, then epilogue ---------
    MBARRIER_WAIT_PARITY(done_a, 0);
    TCGEN05_FENCE_AFTER();

    if (tid < 256) {
        const int mh = tid >> 7;                          // M-half
        const int wg = tid & 127;                         // lane row in half
        const uint32_t woff = (uint32_t)(wg >> 5) << 21;  // TMEM lane-group
        const int rowg = row0 + mh * 128 + wg;
        const int lab = labels[rowg];
        const uint32_t dbase = tmem + mh * 256 + woff;

        float smin = INFINITY, nsum = 0.0f;
        #pragma unroll
        for (int cb = 0; cb < 8; ++cb) {
            uint32_t regs[32];
            TCGEN05_LD_X32(regs, dbase + cb * 32);
            TCGEN05_WAIT_LD();
            #pragma unroll
            for (int c = 0; c < 32; ++c) {
                float sv = __uint_as_float(regs[c]);
                int cl = slab[cb * 32 + c];
                if (cl == lab) smin = fminf(smin, sv);
                else           nsum += ex2f(sv * SCALE_LOG2E);
            }
        }
        float pmin = ex2f(smin * SCALE_LOG2E);
        size_t slot = (size_t)rowg * NSPL + nblk;
        g_pmin[slot] = pmin;
        g_nsum[slot] = nsum;
    }

    __syncthreads();
    if (wid == 0) { TCGEN05_RELINQ(); TCGEN05_DEALLOC(tmem, 512); }
}

#else
// ===========================================================================
// Fallback (plain sm_103 pass only; never selected at runtime on GB300)
// ===========================================================================
__global__ __launch_bounds__(NTHREADS)
void gemm_kernel(const int* __restrict__ labels, const int* __restrict__ labels_s)
{
    __shared__ float As[16][64];
    __shared__ float Bs[16][64];
    __shared__ float red_min[64][16];
    __shared__ float red_sum[64][16];

    const int tid  = threadIdx.x;
    if (tid >= 256) return;
    const int nblk = blockIdx.x;   // 0..63
    const int mblk = blockIdx.y;   // 0..7
    const int tx   = tid & 15;
    const int ty   = tid >> 4;
    const int lr   = tid >> 2;
    const int lk4  = (tid & 3) * 4;

    for (int msub = 0; msub < 4; ++msub) {
        const int row0 = mblk * BM + msub * 64;
        int labr[4];
        #pragma unroll
        for (int i = 0; i < 4; ++i) labr[i] = labels[row0 + ty * 4 + i];

        float fm = INFINITY, fs = 0.0f;
        for (int nsub = 0; nsub < 4; ++nsub) {
            const int col0 = nblk * BN + nsub * 64;
            int labc[4];
            #pragma unroll
            for (int j = 0; j < 4; ++j) labc[j] = labels_s[col0 + tx * 4 + j];

            float acc[4][4];
            #pragma unroll
            for (int i = 0; i < 4; ++i)
                #pragma unroll
                for (int j = 0; j < 4; ++j) acc[i][j] = 0.0f;

            for (int k0 = 0; k0 < CC; k0 += 16) {
                const __nv_bfloat162* ap = (const __nv_bfloat162*)
                    (g_A + (size_t)(row0 + lr) * CC + k0 + lk4);
                const __nv_bfloat162* bp = (const __nv_bfloat162*)
                    (g_B + (size_t)(col0 + lr) * CC + k0 + lk4);
                __nv_bfloat162 a01 = ap[0], a23 = ap[1];
                __nv_bfloat162 b01 = bp[0], b23 = bp[1];
                __syncthreads();
                As[lk4 + 0][lr] = __bfloat162float(a01.x);
                As[lk4 + 1][lr] = __bfloat162float(a01.y);
                As[lk4 + 2][lr] = __bfloat162float(a23.x);
                As[lk4 + 3][lr] = __bfloat162float(a23.y);
                Bs[lk4 + 0][lr] = __bfloat162float(b01.x);
                Bs[lk4 + 1][lr] = __bfloat162float(b01.y);
                Bs[lk4 + 2][lr] = __bfloat162float(b23.x);
                Bs[lk4 + 3][lr] = __bfloat162float(b23.y);
                __syncthreads();
                #pragma unroll
                for (int kk = 0; kk < 16; ++kk) {
                    float4 a = *(const float4*)&As[kk][ty * 4];
                    float4 b = *(const float4*)&Bs[kk][tx * 4];
                    acc[0][0] += a.x * b.x; acc[0][1] += a.x * b.y;
                    acc[0][2] += a.x * b.z; acc[0][3] += a.x * b.w;
                    acc[1][0] += a.y * b.x; acc[1][1] += a.y * b.y;
                    acc[1][2] += a.y * b.z; acc[1][3] += a.y * b.w;
                    acc[2][0] += a.z * b.x; acc[2][1] += a.z * b.y;
                    acc[2][2] += a.z * b.z; acc[2][3] += a.z * b.w;
                    acc[3][0] += a.w * b.x; acc[3][1] += a.w * b.y;
                    acc[3][2] += a.w * b.z; acc[3][3] += a.w * b.w;
                }
            }

            #pragma unroll
            for (int i = 0; i < 4; ++i) {
                float pmin = INFINITY, nsum = 0.0f;
                #pragma unroll
                for (int j = 0; j < 4; ++j) {
                    float e = expf(acc[i][j] * INV_TEMP);
                    if (labr[i] == labc[j]) pmin = fminf(pmin, e);
                    else                    nsum += e;
                }
                red_min[ty * 4 + i][tx] = pmin;
                red_sum[ty * 4 + i][tx] = nsum;
            }
            __syncthreads();
            if (tid < 64) {
                #pragma unroll
                for (int t = 0; t < 16; ++t) {
                    fm = fminf(fm, red_min[tid][t]);
                    fs += red_sum[tid][t];
                }
            }
            __syncthreads();
        }
        if (tid < 64) {
            size_t slot = (size_t)(row0 + tid) * NSPL + nblk;
            g_pmin[slot] = fm;
            g_nsum[slot] = fs;
        }
    }
}
#endif  // USE_TCGEN05

// ---------------- fused per-row loss + mean (last-block reduction) ----------
__global__ void loss_kernel(float* __restrict__ out)
{
    __shared__ float red[256];
    __shared__ int amLast;
    const int tid  = threadIdx.x;
    const int lane = tid & 31;
    const int row  = blockIdx.x * 8 + (tid >> 5);

    float2 pm = ((const float2*)(g_pmin + (size_t)row * NSPL))[lane];
    float2 ns = ((const float2*)(g_nsum + (size_t)row * NSPL))[lane];
    float m = fminf(pm.x, pm.y);
    float s = ns.x + ns.y;
    #pragma unroll
    for (int off = 16; off > 0; off >>= 1) {
        m = fminf(m, __shfl_xor_sync(0xFFFFFFFF, m, off));
        s += __shfl_xor_sync(0xFFFFFFFF, s, off);
    }
    if (lane == 0)
        g_loss[row] = -logf(m / (m + s + 1e-6f) + 1e-6f);

    __threadfence();
    __syncthreads();
    if (tid == 0) amLast = (atomicAdd(&g_count, 1) == (BB / 8) - 1);
    __syncthreads();
    if (amLast) {
        __threadfence();
        float s2 = 0.0f;
        for (int r = tid; r < BB; r += 256) s2 += g_loss[r];
        red[tid] = s2;
        __syncthreads();
        for (int off = 128; off > 0; off >>= 1) {
            if (tid < off) red[tid] += red[tid + off];
            __syncthreads();
        }
        if (tid == 0) { out[0] = red[0] / (float)BB; g_count = 0; }
    }
}

extern "C" void kernel_launch(void* const* d_in, const int* in_sizes, int n_in,
                              void* d_out, int out_size)
{
    const float* feats    = (const float*)d_in[0];
    const float* feats_s  = (const float*)d_in[1];
    const int*   labels   = (const int*)d_in[2];
    const int*   labels_s = (const int*)d_in[3];
    float* out = (float*)d_out;

    cudaFuncSetAttribute(gemm_kernel, cudaFuncAttributeMaxDynamicSharedMemorySize,
                         DSMEM_BYTES);

    cvt_kernel<<<(NA8 + NB8 + 255) / 256, 256>>>((const float4*)feats,
                                                 (const float4*)feats_s);
    dim3 grid(NN / BN, BB / BM);   // (64, 8)
    gemm_kernel<<<grid, NTHREADS, DSMEM_BYTES>>>(labels, labels_s);
    loss_kernel<<<BB / 8, 256>>>(out);
}